// round 1
// baseline (speedup 1.0000x reference)
#include <cuda_runtime.h>
#include <math.h>

// Backflow transform, periodic box.
//   x_w = x - L*floor(x/L)
//   rij = xi - xj;  rij -= L*rint(rij/L)   (minimum image)
//   fr  = 0.5*(exp(-(b/d)^5) - 1),  zero contribution on diagonal (rij=0)
//   out_i = x_w_i + sum_j fr_ij * rij
//
// exp(-(b/d)^5) = 2^(C * rsqrt(r2)^5),  C = -b^5*log2(e)  -> single MUFU.EX2
// Diagonal: r2=0 -> rsqrt=inf -> arg=-inf -> ex2=0 -> s=-0.5, times rij=0 -> 0. No branch.

#define NPART  2048
#define NBATCH 8
#define TPB    128
#define JSPLIT 4                       // warps per block (j-range split)
#define ITILE  32                      // i rows per block (one per lane)
#define BLOCKS_PER_BATCH (NPART / ITILE)   // 64
#define JCHUNK (NPART / JSPLIT)        // 512 iterations per thread

__global__ __launch_bounds__(TPB) void backflow_kernel(
    const float* __restrict__ x, float* __restrict__ out,
    float Lf, float invLf, float C)
{
    __shared__ float4 xs[NPART];                 // wrapped positions, 32 KB
    __shared__ float  red[JSPLIT][3][ITILE];     // cross-warp partials

    const int blk   = blockIdx.x;
    const int b     = blk >> 6;                  // blk / BLOCKS_PER_BATCH
    const int itile = blk & 63;
    const float* __restrict__ xb = x + b * (NPART * 3);

    // Load batch positions, wrap into [0, L). Division (not *invL) to match
    // the reference's floor(x/L) exactly at the boundary.
    for (int p = threadIdx.x; p < NPART; p += TPB) {
        float xx = xb[3 * p + 0];
        float yy = xb[3 * p + 1];
        float zz = xb[3 * p + 2];
        xx -= Lf * floorf(xx / Lf);
        yy -= Lf * floorf(yy / Lf);
        zz -= Lf * floorf(zz / Lf);
        xs[p] = make_float4(xx, yy, zz, 0.0f);
    }
    __syncthreads();

    const int lane = threadIdx.x & 31;
    const int w    = threadIdx.x >> 5;           // 0..JSPLIT-1
    const int i    = itile * ITILE + lane;

    const float4 xi = xs[i];
    float ax = 0.0f, ay = 0.0f, az = 0.0f;

    const int j0 = w * JCHUNK;
    #pragma unroll 8
    for (int jj = 0; jj < JCHUNK; ++jj) {
        // All 32 lanes read the same j -> LDS.128 broadcast, conflict-free.
        float4 xj = xs[j0 + jj];
        float dx = xi.x - xj.x;
        float dy = xi.y - xj.y;
        float dz = xi.z - xj.z;
        dx -= Lf * rintf(dx * invLf);            // minimum image
        dy -= Lf * rintf(dy * invLf);
        dz -= Lf * rintf(dz * invLf);
        float r2   = fmaf(dx, dx, fmaf(dy, dy, dz * dz));
        float inv  = rsqrtf(r2);                 // MUFU.RSQ
        float inv2 = inv * inv;
        float inv4 = inv2 * inv2;
        float arg  = (inv4 * inv) * C;           // C * inv^5 = -b^5*log2e / d^5
        float e;
        asm("ex2.approx.ftz.f32 %0, %1;" : "=f"(e) : "f"(arg));  // MUFU.EX2
        float s = fmaf(e, 0.5f, -0.5f);          // fr
        ax = fmaf(s, dx, ax);
        ay = fmaf(s, dy, ay);
        az = fmaf(s, dz, az);
    }

    red[w][0][lane] = ax;
    red[w][1][lane] = ay;
    red[w][2][lane] = az;
    __syncthreads();

    // Deterministic cross-warp reduction + output write (96 active threads).
    const int t = threadIdx.x;
    if (t < 3 * ITILE) {
        const int d  = t / ITILE;       // dim 0..2
        const int il = t % ITILE;       // local i
        float s = red[0][d][il] + red[1][d][il] + red[2][d][il] + red[3][d][il];
        float4 xv = xs[itile * ITILE + il];
        float base = (d == 0) ? xv.x : ((d == 1) ? xv.y : xv.z);
        out[b * (NPART * 3) + (itile * ITILE + il) * 3 + d] = base + s;
    }
}

extern "C" void kernel_launch(void* const* d_in, const int* in_sizes, int n_in,
                              void* d_out, int out_size) {
    const float* x = (const float*)d_in[0];
    float* out = (float*)d_out;

    // Match the Python reference constants (computed in double, cast to float).
    const double Ld = pow((double)NPART / 0.016355, 1.0 / 3.0);
    const float  Lf    = (float)Ld;
    const float  invLf = (float)(1.0 / Ld);
    const double b5    = pow(2.6, 5.0);                     // 118.81376
    const float  C     = (float)(-b5 * 1.4426950408889634); // -b^5 * log2(e)

    backflow_kernel<<<NBATCH * BLOCKS_PER_BATCH, TPB>>>(x, out, Lf, invLf, C);
}

// round 2
// speedup vs baseline: 1.2266x; 1.2266x over previous
#include <cuda_runtime.h>
#include <math.h>

// Backflow transform, periodic box — packed f32x2 version.
//   fr(d) = 0.5*(exp(-(b/d)^5) - 1);  out_i = wrap(x_i) + sum_j fr_ij * rij
// exp(-(b/d)^5) = 2^(C * rsqrt(r2)^5), C = -b^5*log2(e)  -> one MUFU.EX2 per pair.
// Diagonal: r2=0 -> rsqrt=inf -> arg=-inf -> ex2=0 -> s=-0.5, times rij=0 -> 0.
// Two j's per lane packed in 64-bit f32x2 registers (FFMA2 path, PTX-only).
// rint via magic constant 1.5*2^23 (exact round-to-nearest-even for |t| < 1).

#define NPART  2048
#define NBATCH 8
#define TPB    128
#define JSPLIT 4                       // warps per block (j-range split)
#define ITILE  32                      // i rows per block (one per lane)
#define JCHUNK (NPART / JSPLIT)        // 512 j's per warp -> 256 packed iters

typedef unsigned long long u64;

__device__ __forceinline__ u64 pk2(float lo, float hi) {
    u64 r; asm("mov.b64 %0, {%1,%2};" : "=l"(r) : "f"(lo), "f"(hi)); return r;
}
__device__ __forceinline__ void upk2(u64 v, float& lo, float& hi) {
    asm("mov.b64 {%0,%1}, %2;" : "=f"(lo), "=f"(hi) : "l"(v));
}
__device__ __forceinline__ u64 fma2_(u64 a, u64 b, u64 c) {
    u64 d; asm("fma.rn.f32x2 %0,%1,%2,%3;" : "=l"(d) : "l"(a), "l"(b), "l"(c)); return d;
}
__device__ __forceinline__ u64 add2_(u64 a, u64 b) {
    u64 d; asm("add.rn.f32x2 %0,%1,%2;" : "=l"(d) : "l"(a), "l"(b)); return d;
}
__device__ __forceinline__ u64 mul2_(u64 a, u64 b) {
    u64 d; asm("mul.rn.f32x2 %0,%1,%2;" : "=l"(d) : "l"(a), "l"(b)); return d;
}
__device__ __forceinline__ float ex2f(float x) {
    float r; asm("ex2.approx.ftz.f32 %0, %1;" : "=f"(r) : "f"(x)); return r;
}

#define MAGICF 12582912.0f  // 1.5 * 2^23

__global__ __launch_bounds__(TPB) void backflow_kernel(
    const float* __restrict__ x, float* __restrict__ out,
    float Lf, float invLf, float C)
{
    __shared__ __align__(16) float sx[NPART];   // NEGATED wrapped positions (SoA)
    __shared__ __align__(16) float sy[NPART];
    __shared__ __align__(16) float sz[NPART];
    __shared__ float red[JSPLIT][3][ITILE];

    const int blk   = blockIdx.x;
    const int b     = blk >> 6;                 // blk / (NPART/ITILE)
    const int itile = blk & 63;
    const float* __restrict__ xb = x + b * (NPART * 3);

    // Load, wrap into [0,L) (divide to match reference's floor(x/L)), store negated.
    for (int p = threadIdx.x; p < NPART; p += TPB) {
        float xx = xb[3 * p + 0];
        float yy = xb[3 * p + 1];
        float zz = xb[3 * p + 2];
        xx -= Lf * floorf(xx / Lf);
        yy -= Lf * floorf(yy / Lf);
        zz -= Lf * floorf(zz / Lf);
        sx[p] = -xx; sy[p] = -yy; sz[p] = -zz;
    }
    __syncthreads();

    const int lane = threadIdx.x & 31;
    const int w    = threadIdx.x >> 5;
    const int i    = itile * ITILE + lane;

    const float xi_x = -sx[i], xi_y = -sy[i], xi_z = -sz[i];
    const u64 xix = pk2(xi_x, xi_x);
    const u64 xiy = pk2(xi_y, xi_y);
    const u64 xiz = pk2(xi_z, xi_z);

    const u64 invL2  = pk2(invLf, invLf);
    const u64 negL2  = pk2(-Lf, -Lf);
    const u64 MAG2   = pk2(MAGICF, MAGICF);
    const u64 NMAG2  = pk2(-MAGICF, -MAGICF);
    const u64 C2     = pk2(C, C);
    const u64 H2     = pk2(0.5f, 0.5f);
    const u64 NH2    = pk2(-0.5f, -0.5f);

    const u64* __restrict__ sx2 = (const u64*)sx;
    const u64* __restrict__ sy2 = (const u64*)sy;
    const u64* __restrict__ sz2 = (const u64*)sz;

    u64 axp = 0ull, ayp = 0ull, azp = 0ull;     // packed (0.0f, 0.0f)

    const int base = (w * JCHUNK) >> 1;
    #pragma unroll 8
    for (int jj = 0; jj < JCHUNK / 2; ++jj) {
        // All lanes read the same address -> LDS.64 broadcast, conflict-free.
        u64 nxj = sx2[base + jj];               // (-xj0.x, -xj1.x)
        u64 nyj = sy2[base + jj];
        u64 nzj = sz2[base + jj];
        u64 dx = add2_(xix, nxj);               // xi - xj, two pairs at once
        u64 dy = add2_(xiy, nyj);
        u64 dz = add2_(xiz, nzj);
        // minimum image: dx -= L * rint(dx/L), rint via magic (RNE, |t|<1)
        u64 tx = fma2_(dx, invL2, MAG2);
        u64 ty = fma2_(dy, invL2, MAG2);
        u64 tz = fma2_(dz, invL2, MAG2);
        u64 rx = add2_(tx, NMAG2);
        u64 ry = add2_(ty, NMAG2);
        u64 rz = add2_(tz, NMAG2);
        dx = fma2_(rx, negL2, dx);
        dy = fma2_(ry, negL2, dy);
        dz = fma2_(rz, negL2, dz);
        u64 r2 = mul2_(dx, dx);
        r2 = fma2_(dy, dy, r2);
        r2 = fma2_(dz, dz, r2);
        float r2a, r2b; upk2(r2, r2a, r2b);     // free: register-pair halves
        float inva = rsqrtf(r2a);               // MUFU.RSQ x2
        float invb = rsqrtf(r2b);
        u64 invp = pk2(inva, invb);
        u64 i2  = mul2_(invp, invp);
        u64 i4  = mul2_(i2, i2);
        u64 i5  = mul2_(i4, invp);
        u64 arg = mul2_(i5, C2);                // C * inv^5
        float aa, ab; upk2(arg, aa, ab);
        u64 ep = pk2(ex2f(aa), ex2f(ab));       // MUFU.EX2 x2
        u64 s  = fma2_(ep, H2, NH2);            // fr = 0.5*e - 0.5
        axp = fma2_(s, dx, axp);
        ayp = fma2_(s, dy, ayp);
        azp = fma2_(s, dz, azp);
    }

    float alo, ahi;
    upk2(axp, alo, ahi); red[w][0][lane] = alo + ahi;
    upk2(ayp, alo, ahi); red[w][1][lane] = alo + ahi;
    upk2(azp, alo, ahi); red[w][2][lane] = alo + ahi;
    __syncthreads();

    // Deterministic cross-warp reduction + output (96 active threads).
    const int t = threadIdx.x;
    if (t < 3 * ITILE) {
        const int d  = t / ITILE;
        const int il = t % ITILE;
        float s = red[0][d][il] + red[1][d][il] + red[2][d][il] + red[3][d][il];
        const int ig = itile * ITILE + il;
        float basev = (d == 0) ? -sx[ig] : ((d == 1) ? -sy[ig] : -sz[ig]);
        out[b * (NPART * 3) + ig * 3 + d] = basev + s;
    }
}

extern "C" void kernel_launch(void* const* d_in, const int* in_sizes, int n_in,
                              void* d_out, int out_size) {
    const float* x = (const float*)d_in[0];
    float* out = (float*)d_out;

    const double Ld = pow((double)NPART / 0.016355, 1.0 / 3.0);
    const float  Lf    = (float)Ld;
    const float  invLf = (float)(1.0 / Ld);
    const double b5    = pow(2.6, 5.0);                     // 118.81376
    const float  C     = (float)(-b5 * 1.4426950408889634); // -b^5 * log2(e)

    backflow_kernel<<<NBATCH * (NPART / ITILE), TPB>>>(x, out, Lf, invLf, C);
}

// round 3
// speedup vs baseline: 1.3322x; 1.0861x over previous
#include <cuda_runtime.h>
#include <math.h>

// Backflow transform, periodic box — packed f32x2, 8 warps/block for latency hiding.
//   fr(d) = 0.5*(exp(-(b/d)^5) - 1);  out_i = wrap(x_i) + sum_j fr_ij * rij
// exp(-(b/d)^5) = 2^(C * rsqrt(r2)^5), C = -b^5*log2(e)  -> one MUFU.EX2 per pair.
// Diagonal: r2=0 -> rsqrt=inf -> arg=-inf -> ex2=0 -> s=-0.5, times rij=0 -> 0.
// Two j's per lane packed in 64-bit f32x2 registers (FFMA2 path, PTX-only).
// rint via magic constant 1.5*2^23 (exact round-to-nearest-even for |t| < 1).

#define NPART  2048
#define NBATCH 8
#define TPB    256
#define JSPLIT 8                       // warps per block (j-range split)
#define ITILE  32                      // i rows per block (one per lane)
#define JCHUNK (NPART / JSPLIT)        // 256 j's per warp -> 128 packed iters

typedef unsigned long long u64;

__device__ __forceinline__ u64 pk2(float lo, float hi) {
    u64 r; asm("mov.b64 %0, {%1,%2};" : "=l"(r) : "f"(lo), "f"(hi)); return r;
}
__device__ __forceinline__ void upk2(u64 v, float& lo, float& hi) {
    asm("mov.b64 {%0,%1}, %2;" : "=f"(lo), "=f"(hi) : "l"(v));
}
__device__ __forceinline__ u64 fma2_(u64 a, u64 b, u64 c) {
    u64 d; asm("fma.rn.f32x2 %0,%1,%2,%3;" : "=l"(d) : "l"(a), "l"(b), "l"(c)); return d;
}
__device__ __forceinline__ u64 add2_(u64 a, u64 b) {
    u64 d; asm("add.rn.f32x2 %0,%1,%2;" : "=l"(d) : "l"(a), "l"(b)); return d;
}
__device__ __forceinline__ u64 mul2_(u64 a, u64 b) {
    u64 d; asm("mul.rn.f32x2 %0,%1,%2;" : "=l"(d) : "l"(a), "l"(b)); return d;
}
__device__ __forceinline__ float ex2f(float x) {
    float r; asm("ex2.approx.ftz.f32 %0, %1;" : "=f"(r) : "f"(x)); return r;
}

#define MAGICF 12582912.0f  // 1.5 * 2^23

__global__ __launch_bounds__(TPB, 3) void backflow_kernel(
    const float* __restrict__ x, float* __restrict__ out,
    float Lf, float invLf, float C)
{
    __shared__ __align__(16) float sx[NPART];   // NEGATED wrapped positions (SoA)
    __shared__ __align__(16) float sy[NPART];
    __shared__ __align__(16) float sz[NPART];
    __shared__ float red[JSPLIT][3][ITILE];

    const int blk   = blockIdx.x;
    const int b     = blk >> 6;                 // blk / (NPART/ITILE)
    const int itile = blk & 63;
    const float* __restrict__ xb = x + b * (NPART * 3);

    // Load, wrap into [0,L) (divide to match reference's floor(x/L)), store negated.
    for (int p = threadIdx.x; p < NPART; p += TPB) {
        float xx = xb[3 * p + 0];
        float yy = xb[3 * p + 1];
        float zz = xb[3 * p + 2];
        xx -= Lf * floorf(xx / Lf);
        yy -= Lf * floorf(yy / Lf);
        zz -= Lf * floorf(zz / Lf);
        sx[p] = -xx; sy[p] = -yy; sz[p] = -zz;
    }
    __syncthreads();

    const int lane = threadIdx.x & 31;
    const int w    = threadIdx.x >> 5;          // 0..JSPLIT-1
    const int i    = itile * ITILE + lane;

    const float xi_x = -sx[i], xi_y = -sy[i], xi_z = -sz[i];
    const u64 xix = pk2(xi_x, xi_x);
    const u64 xiy = pk2(xi_y, xi_y);
    const u64 xiz = pk2(xi_z, xi_z);

    const u64 invL2  = pk2(invLf, invLf);
    const u64 negL2  = pk2(-Lf, -Lf);
    const u64 MAG2   = pk2(MAGICF, MAGICF);
    const u64 NMAG2  = pk2(-MAGICF, -MAGICF);
    const u64 C2     = pk2(C, C);
    const u64 H2     = pk2(0.5f, 0.5f);
    const u64 NH2    = pk2(-0.5f, -0.5f);

    const u64* __restrict__ sx2 = (const u64*)sx;
    const u64* __restrict__ sy2 = (const u64*)sy;
    const u64* __restrict__ sz2 = (const u64*)sz;

    u64 axp = 0ull, ayp = 0ull, azp = 0ull;     // packed (0.0f, 0.0f)

    const int base = (w * JCHUNK) >> 1;
    #pragma unroll 8
    for (int jj = 0; jj < JCHUNK / 2; ++jj) {
        // All lanes read the same address -> LDS.64 broadcast, conflict-free.
        u64 nxj = sx2[base + jj];               // (-xj0.x, -xj1.x)
        u64 nyj = sy2[base + jj];
        u64 nzj = sz2[base + jj];
        u64 dx = add2_(xix, nxj);               // xi - xj, two pairs at once
        u64 dy = add2_(xiy, nyj);
        u64 dz = add2_(xiz, nzj);
        // minimum image: dx -= L * rint(dx/L), rint via magic (RNE, |t|<1)
        u64 tx = fma2_(dx, invL2, MAG2);
        u64 ty = fma2_(dy, invL2, MAG2);
        u64 tz = fma2_(dz, invL2, MAG2);
        u64 rx = add2_(tx, NMAG2);
        u64 ry = add2_(ty, NMAG2);
        u64 rz = add2_(tz, NMAG2);
        dx = fma2_(rx, negL2, dx);
        dy = fma2_(ry, negL2, dy);
        dz = fma2_(rz, negL2, dz);
        u64 r2 = mul2_(dx, dx);
        r2 = fma2_(dy, dy, r2);
        r2 = fma2_(dz, dz, r2);
        float r2a, r2b; upk2(r2, r2a, r2b);     // free: register-pair halves
        float inva = rsqrtf(r2a);               // MUFU.RSQ x2
        float invb = rsqrtf(r2b);
        u64 invp = pk2(inva, invb);
        u64 i2  = mul2_(invp, invp);
        u64 i4  = mul2_(i2, i2);
        u64 i5  = mul2_(i4, invp);
        u64 arg = mul2_(i5, C2);                // C * inv^5
        float aa, ab; upk2(arg, aa, ab);
        u64 ep = pk2(ex2f(aa), ex2f(ab));       // MUFU.EX2 x2
        u64 s  = fma2_(ep, H2, NH2);            // fr = 0.5*e - 0.5
        axp = fma2_(s, dx, axp);
        ayp = fma2_(s, dy, ayp);
        azp = fma2_(s, dz, azp);
    }

    float alo, ahi;
    upk2(axp, alo, ahi); red[w][0][lane] = alo + ahi;
    upk2(ayp, alo, ahi); red[w][1][lane] = alo + ahi;
    upk2(azp, alo, ahi); red[w][2][lane] = alo + ahi;
    __syncthreads();

    // Deterministic cross-warp reduction + output (96 active threads).
    const int t = threadIdx.x;
    if (t < 3 * ITILE) {
        const int d  = t / ITILE;
        const int il = t % ITILE;
        float s = 0.0f;
        #pragma unroll
        for (int ww = 0; ww < JSPLIT; ++ww) s += red[ww][d][il];
        const int ig = itile * ITILE + il;
        float basev = (d == 0) ? -sx[ig] : ((d == 1) ? -sy[ig] : -sz[ig]);
        out[b * (NPART * 3) + ig * 3 + d] = basev + s;
    }
}

extern "C" void kernel_launch(void* const* d_in, const int* in_sizes, int n_in,
                              void* d_out, int out_size) {
    const float* x = (const float*)d_in[0];
    float* out = (float*)d_out;

    const double Ld = pow((double)NPART / 0.016355, 1.0 / 3.0);
    const float  Lf    = (float)Ld;
    const float  invLf = (float)(1.0 / Ld);
    const double b5    = pow(2.6, 5.0);                     // 118.81376
    const float  C     = (float)(-b5 * 1.4426950408889634); // -b^5 * log2(e)

    backflow_kernel<<<NBATCH * (NPART / ITILE), TPB>>>(x, out, Lf, invLf, C);
}

// round 4
// speedup vs baseline: 1.4845x; 1.1143x over previous
#include <cuda_runtime.h>
#include <math.h>

// Backflow transform, periodic box — packed f32x2, single-wave residency (4 blocks/SM).
//   fr(d) = 0.5*(exp(-(b/d)^5) - 1);  out_i = wrap(x_i) + sum_j fr_ij * rij
// exp(-(b/d)^5) = 2^(C * rsqrt(r2)^5), C = -b^5*log2(e)  -> one MUFU.EX2 per pair.
// Diagonal: r2=0 -> rsqrt=inf -> arg=-inf -> ex2=0 -> s=-0.5, times rij=0 -> 0.
// Two j's per lane packed in 64-bit f32x2 registers (FFMA2 path, PTX-only).
// rint via magic constant 1.5*2^23 (exact round-to-nearest-even for |t| < 1).
// rsqrt via explicit MUFU (rsqrt.approx.ftz) — avoids the precise-refinement expansion.

#define NPART  2048
#define NBATCH 8
#define TPB    256
#define JSPLIT 8                       // warps per block (j-range split)
#define ITILE  32                      // i rows per block (one per lane)
#define JCHUNK (NPART / JSPLIT)        // 256 j's per warp -> 128 packed iters

typedef unsigned long long u64;

__device__ __forceinline__ u64 pk2(float lo, float hi) {
    u64 r; asm("mov.b64 %0, {%1,%2};" : "=l"(r) : "f"(lo), "f"(hi)); return r;
}
__device__ __forceinline__ void upk2(u64 v, float& lo, float& hi) {
    asm("mov.b64 {%0,%1}, %2;" : "=f"(lo), "=f"(hi) : "l"(v));
}
__device__ __forceinline__ u64 fma2_(u64 a, u64 b, u64 c) {
    u64 d; asm("fma.rn.f32x2 %0,%1,%2,%3;" : "=l"(d) : "l"(a), "l"(b), "l"(c)); return d;
}
__device__ __forceinline__ u64 add2_(u64 a, u64 b) {
    u64 d; asm("add.rn.f32x2 %0,%1,%2;" : "=l"(d) : "l"(a), "l"(b)); return d;
}
__device__ __forceinline__ u64 mul2_(u64 a, u64 b) {
    u64 d; asm("mul.rn.f32x2 %0,%1,%2;" : "=l"(d) : "l"(a), "l"(b)); return d;
}
__device__ __forceinline__ float ex2f(float x) {
    float r; asm("ex2.approx.ftz.f32 %0, %1;" : "=f"(r) : "f"(x)); return r;
}
__device__ __forceinline__ float rsq_(float x) {
    float r; asm("rsqrt.approx.ftz.f32 %0, %1;" : "=f"(r) : "f"(x)); return r;
}

#define MAGICF 12582912.0f  // 1.5 * 2^23

__global__ __launch_bounds__(TPB, 4) void backflow_kernel(
    const float* __restrict__ x, float* __restrict__ out,
    float Lf, float invLf, float C)
{
    __shared__ __align__(16) float sx[NPART];   // NEGATED wrapped positions (SoA)
    __shared__ __align__(16) float sy[NPART];
    __shared__ __align__(16) float sz[NPART];
    __shared__ float red[JSPLIT][3][ITILE];

    const int blk   = blockIdx.x;
    const int b     = blk >> 6;                 // blk / (NPART/ITILE)
    const int itile = blk & 63;
    const float* __restrict__ xb = x + b * (NPART * 3);

    // Load, wrap into [0,L) (divide to match reference's floor(x/L)), store negated.
    for (int p = threadIdx.x; p < NPART; p += TPB) {
        float xx = xb[3 * p + 0];
        float yy = xb[3 * p + 1];
        float zz = xb[3 * p + 2];
        xx -= Lf * floorf(xx / Lf);
        yy -= Lf * floorf(yy / Lf);
        zz -= Lf * floorf(zz / Lf);
        sx[p] = -xx; sy[p] = -yy; sz[p] = -zz;
    }
    __syncthreads();

    const int lane = threadIdx.x & 31;
    const int w    = threadIdx.x >> 5;          // 0..JSPLIT-1
    const int i    = itile * ITILE + lane;

    const float xi_x = -sx[i], xi_y = -sy[i], xi_z = -sz[i];
    const u64 xix = pk2(xi_x, xi_x);
    const u64 xiy = pk2(xi_y, xi_y);
    const u64 xiz = pk2(xi_z, xi_z);

    const u64 invL2  = pk2(invLf, invLf);
    const u64 negL2  = pk2(-Lf, -Lf);
    const u64 MAG2   = pk2(MAGICF, MAGICF);
    const u64 NMAG2  = pk2(-MAGICF, -MAGICF);
    const u64 C2     = pk2(C, C);
    const u64 H2     = pk2(0.5f, 0.5f);
    const u64 NH2    = pk2(-0.5f, -0.5f);

    const u64* __restrict__ sx2 = (const u64*)sx;
    const u64* __restrict__ sy2 = (const u64*)sy;
    const u64* __restrict__ sz2 = (const u64*)sz;

    u64 axp = 0ull, ayp = 0ull, azp = 0ull;     // packed (0.0f, 0.0f)

    const int base = (w * JCHUNK) >> 1;
    #pragma unroll 4
    for (int jj = 0; jj < JCHUNK / 2; ++jj) {
        // All lanes read the same address -> LDS.64 broadcast, conflict-free.
        u64 nxj = sx2[base + jj];               // (-xj0.x, -xj1.x)
        u64 nyj = sy2[base + jj];
        u64 nzj = sz2[base + jj];
        u64 dx = add2_(xix, nxj);               // xi - xj, two pairs at once
        u64 dy = add2_(xiy, nyj);
        u64 dz = add2_(xiz, nzj);
        // minimum image: dx -= L * rint(dx/L), rint via magic (RNE, |t|<1)
        u64 tx = fma2_(dx, invL2, MAG2);
        u64 ty = fma2_(dy, invL2, MAG2);
        u64 tz = fma2_(dz, invL2, MAG2);
        u64 rx = add2_(tx, NMAG2);
        u64 ry = add2_(ty, NMAG2);
        u64 rz = add2_(tz, NMAG2);
        dx = fma2_(rx, negL2, dx);
        dy = fma2_(ry, negL2, dy);
        dz = fma2_(rz, negL2, dz);
        u64 r2 = mul2_(dx, dx);
        r2 = fma2_(dy, dy, r2);
        r2 = fma2_(dz, dz, r2);
        float r2a, r2b; upk2(r2, r2a, r2b);     // free: register-pair halves
        u64 invp = pk2(rsq_(r2a), rsq_(r2b));   // MUFU.RSQ x2
        u64 i2  = mul2_(invp, invp);
        u64 i4  = mul2_(i2, i2);
        u64 i5  = mul2_(i4, invp);
        u64 arg = mul2_(i5, C2);                // C * inv^5
        float aa, ab; upk2(arg, aa, ab);
        u64 ep = pk2(ex2f(aa), ex2f(ab));       // MUFU.EX2 x2
        u64 s  = fma2_(ep, H2, NH2);            // fr = 0.5*e - 0.5
        axp = fma2_(s, dx, axp);
        ayp = fma2_(s, dy, ayp);
        azp = fma2_(s, dz, azp);
    }

    float alo, ahi;
    upk2(axp, alo, ahi); red[w][0][lane] = alo + ahi;
    upk2(ayp, alo, ahi); red[w][1][lane] = alo + ahi;
    upk2(azp, alo, ahi); red[w][2][lane] = alo + ahi;
    __syncthreads();

    // Deterministic cross-warp reduction + output (96 active threads).
    const int t = threadIdx.x;
    if (t < 3 * ITILE) {
        const int d  = t / ITILE;
        const int il = t % ITILE;
        float s = 0.0f;
        #pragma unroll
        for (int ww = 0; ww < JSPLIT; ++ww) s += red[ww][d][il];
        const int ig = itile * ITILE + il;
        float basev = (d == 0) ? -sx[ig] : ((d == 1) ? -sy[ig] : -sz[ig]);
        out[b * (NPART * 3) + ig * 3 + d] = basev + s;
    }
}

extern "C" void kernel_launch(void* const* d_in, const int* in_sizes, int n_in,
                              void* d_out, int out_size) {
    const float* x = (const float*)d_in[0];
    float* out = (float*)d_out;

    const double Ld = pow((double)NPART / 0.016355, 1.0 / 3.0);
    const float  Lf    = (float)Ld;
    const float  invLf = (float)(1.0 / Ld);
    const double b5    = pow(2.6, 5.0);                     // 118.81376
    const float  C     = (float)(-b5 * 1.4426950408889634); // -b^5 * log2(e)

    backflow_kernel<<<NBATCH * (NPART / ITILE), TPB>>>(x, out, Lf, invLf, C);
}